// round 15
// baseline (speedup 1.0000x reference)
#include <cuda_runtime.h>
#include <cuda_bf16.h>
#include <stdint.h>

#define BATCH 2048
#define HW81  81
#define CDIM  512
#define HID   256
#define MPAD  96                  /* 81 rows padded to 6x16 */
#define NSM   152                 /* GB300 SM count */

// W pre-rounded to tf32 (fp32 bit patterns), [256][512]
__device__ float g_Wt[HID * CDIM];

// ---------------------------------------------------------------------------
// helpers
// ---------------------------------------------------------------------------
__device__ __forceinline__ uint32_t f2tf32(float f) {
    uint32_t u;
    asm("cvt.rna.tf32.f32 %0, %1;" : "=r"(u) : "f"(f));
    return u;
}

__device__ __forceinline__ uint32_t smem_u32(const void* p) {
    uint32_t a;
    asm("{ .reg .u64 t; cvta.to.shared.u64 t, %1; cvt.u32.u64 %0, t; }" : "=r"(a) : "l"(p));
    return a;
}

__device__ __forceinline__ void cp16(uint32_t dst, const void* src) {
    asm volatile("cp.async.cg.shared.global [%0], [%1], 16;" :: "r"(dst), "l"(src));
}

__device__ __forceinline__ void mma_tf32(float* c, uint32_t a0, uint32_t a1,
                                         uint32_t a2, uint32_t a3,
                                         uint32_t b0, uint32_t b1) {
    asm volatile(
        "mma.sync.aligned.m16n8k8.row.col.f32.tf32.tf32.f32 "
        "{%0,%1,%2,%3}, {%4,%5,%6,%7}, {%8,%9}, {%0,%1,%2,%3};\n"
        : "+f"(c[0]), "+f"(c[1]), "+f"(c[2]), "+f"(c[3])
        : "r"(a0), "r"(a1), "r"(a2), "r"(a3), "r"(b0), "r"(b1));
}

#define BAR_SYNC(ID, CNT) \
    asm volatile("bar.sync %0, %1;" :: "r"(ID), "r"(CNT) : "memory")
#define BAR_ARRIVE(ID, CNT) \
    asm volatile("bar.arrive %0, %1;" :: "r"(ID), "r"(CNT) : "memory")
#define MEMBAR_CTA() asm volatile("membar.cta;" ::: "memory")

// rm(q,p): row in x-natural order of token q of patch p's attention view
__device__ __forceinline__ int rowmap(int q, int p) {
    return (3 * (q / 3) + p / 3) * 9 + 3 * (q % 3) + (p % 3);
}

// ---------------------------------------------------------------------------
// Kernel 0: round W to tf32 (RNA) once.
// ---------------------------------------------------------------------------
__global__ void wprep_kernel(const float* __restrict__ Wf) {
    int i = blockIdx.x * 512 + threadIdx.x;
    g_Wt[i] = __uint_as_float(f2tf32(Wf[i]));
}

// ---------------------------------------------------------------------------
// Warp-specialized fused kernel.  1 CTA/SM, 512 threads.
//   warps 0-7  (GEMM half): for each assigned batch b: tf32 mma mainloop
//     (R12 shape: 2-stage cp.async, KSTG=32) -> Y(b) into smem.
//   warps 8-15 (ATTN half): for each b: syrk + double softmax from smem-Y,
//     release Y early (after syrk), then epilogue out = P @ x.
//   attn(b) overlaps GEMM mainloop(b+1): tensor pipe never idles for attn.
// Handshake: named barrier 3 = "Y ready", 4 = "Y free"; 1/2 intra-half.
// smem: staging 101376B + Y 82944B = 184320B dyn.
// ---------------------------------------------------------------------------
#define KSTG     32
#define STRIDE   36
#define OFF_A0   0
#define OFF_B0   (MPAD * STRIDE)                 /* 3456  */
#define OFF_A1   (OFF_B0 + HID * STRIDE)         /* 12672 */
#define OFF_B1   (OFF_A1 + MPAD * STRIDE)        /* 16128 */
#define STAGE_FLOATS (OFF_B1 + HID * STRIDE)     /* 25344 floats = 101376 B */
#define SMEM_FLOATS  (STAGE_FLOATS + HW81 * HID) /* + 20736 -> 46080 floats */

__global__ __launch_bounds__(512, 1)
void fused_ws(const float* __restrict__ X, const float* __restrict__ bfc,
              float* __restrict__ out)
{
    extern __shared__ __align__(16) float smem[];
    float* sY = smem + STAGE_FLOATS;             // [81][256]
    __shared__ float sBias[HID];
    __shared__ float sRed[8][45];
    __shared__ float sAttn[81];
    __shared__ float sB2[81];
    __shared__ __align__(16) float sPp[9 * 12];

    const int tid = threadIdx.x;
    const int b0   = (BATCH * blockIdx.x) / NSM;
    const int bEnd = (BATCH * (blockIdx.x + 1)) / NSM;
    const uint32_t sbase = smem_u32(smem);

    if (tid < 256) {
        // ===================== GEMM half (warps 0-7) =====================
        const int lane = tid & 31;
        const int warp = tid >> 5;
        const int wm   = warp >> 2;          // 0..1 (M)
        const int wn   = warp & 3;           // 0..3 (N)

        sBias[tid] = __ldg(bfc + tid);

        const int ar = wm * 48 + (lane >> 2);
        const int ac = lane & 3;
        const int bn = wn * 64 + (lane >> 2);

#define ISSUE_STAGE(XB, IT, OFFA, OFFB)                                      \
    do {                                                                     \
        const int k0 = (IT) * KSTG;                                          \
        _Pragma("unroll")                                                    \
        for (int i = 0; i < 3; i++) {                                        \
            int f = i * 256 + tid;                                           \
            int r = f >> 3, j = (f & 7) << 2;                                \
            int rs = r < HW81 ? r : (HW81 - 1);                              \
            cp16(sbase + ((OFFA) + r * STRIDE + j) * 4,                      \
                 (XB) + (size_t)rs * CDIM + k0 + j);                         \
        }                                                                    \
        _Pragma("unroll")                                                    \
        for (int i = 0; i < 8; i++) {                                        \
            int f = i * 256 + tid;                                           \
            int n = f >> 3, j = (f & 7) << 2;                                \
            cp16(sbase + ((OFFB) + n * STRIDE + j) * 4,                      \
                 g_Wt + (size_t)n * CDIM + k0 + j);                          \
        }                                                                    \
        asm volatile("cp.async.commit_group;" ::: "memory");                 \
    } while (0)

        {
            const float* Xb0 = X + (size_t)b0 * (HW81 * CDIM);
            ISSUE_STAGE(Xb0, 0, OFF_A0, OFF_B0);
            ISSUE_STAGE(Xb0, 1, OFF_A1, OFF_B1);
        }

        for (int b = b0; b < bEnd; b++) {
            const float* Xb  = X + (size_t)b * (HW81 * CDIM);
            const float* Xb1 = X + (size_t)(b + 1) * (HW81 * CDIM);

            float acc[3][8][4];
#pragma unroll
            for (int a = 0; a < 3; a++)
#pragma unroll
                for (int c = 0; c < 8; c++)
#pragma unroll
                    for (int d = 0; d < 4; d++) acc[a][c][d] = 0.f;

            for (int it = 0; it < 16; it++) {
                if (it < 15) asm volatile("cp.async.wait_group 1;" ::: "memory");
                else         asm volatile("cp.async.wait_group 0;" ::: "memory");
                BAR_SYNC(1, 256);

                const float*    sA = smem + ((it & 1) ? OFF_A1 : OFF_A0);
                const uint32_t* sB = (const uint32_t*)(smem + ((it & 1) ? OFF_B1 : OFF_B0));

#pragma unroll
                for (int kk = 0; kk < 4; kk++) {
                    const int c = kk * 8 + ac;
                    uint32_t bf[8][2];
#pragma unroll
                    for (int nt = 0; nt < 8; nt++) {
                        bf[nt][0] = sB[(bn + nt * 8) * STRIDE + c];
                        bf[nt][1] = sB[(bn + nt * 8) * STRIDE + c + 4];
                    }
#pragma unroll
                    for (int mt = 0; mt < 3; mt++) {
                        const int r = ar + mt * 16;
                        uint32_t a0 = f2tf32(sA[r * STRIDE + c]);
                        uint32_t a1 = f2tf32(sA[(r + 8) * STRIDE + c]);
                        uint32_t a2 = f2tf32(sA[r * STRIDE + c + 4]);
                        uint32_t a3 = f2tf32(sA[(r + 8) * STRIDE + c + 4]);
#pragma unroll
                        for (int nt = 0; nt < 8; nt++)
                            mma_tf32(acc[mt][nt], a0, a1, a2, a3, bf[nt][0], bf[nt][1]);
                    }
                }
                BAR_SYNC(1, 256);

                if (it < 14) {
                    if (it & 1) ISSUE_STAGE(Xb, it + 2, OFF_A1, OFF_B1);
                    else        ISSUE_STAGE(Xb, it + 2, OFF_A0, OFF_B0);
                }
            }

            // prefetch first two stages of the NEXT batch (buffers are free;
            // overlaps the Y-free wait + writeback below)
            if (b + 1 < bEnd) {
                ISSUE_STAGE(Xb1, 0, OFF_A0, OFF_B0);
                ISSUE_STAGE(Xb1, 1, OFF_A1, OFF_B1);
            }

            // wait for attn half to finish syrk of the previous batch
            if (b > b0) BAR_SYNC(4, 512);

            // writeback Y + bias into smem
#pragma unroll
            for (int nt = 0; nt < 8; nt++) {
                const int cc = wn * 64 + nt * 8 + ((lane & 3) << 1);
                const float bb0 = sBias[cc];
                const float bb1 = sBias[cc + 1];
#pragma unroll
                for (int mt = 0; mt < 3; mt++) {
                    const int r = ar + mt * 16;
                    if (r < HW81) {
                        sY[r * HID + cc]     = acc[mt][nt][0] + bb0;
                        sY[r * HID + cc + 1] = acc[mt][nt][1] + bb1;
                    }
                    if (r + 8 < HW81) {
                        sY[(r + 8) * HID + cc]     = acc[mt][nt][2] + bb0;
                        sY[(r + 8) * HID + cc + 1] = acc[mt][nt][3] + bb1;
                    }
                }
            }
            MEMBAR_CTA();
            BAR_ARRIVE(3, 512);          // Y(b) ready
        }
    } else {
        // ===================== ATTN half (warps 8-15) =====================
        const int t     = tid - 256;          // 0..255
        const int lane  = t & 31;
        const int warpA = t >> 5;             // 0..7

        for (int b = b0; b < bEnd; b++) {
            BAR_SYNC(3, 512);                 // wait Y(b) ready

            // ---- syrk from sY ----
            float sa[45];
#pragma unroll
            for (int i = 0; i < 45; i++) sa[i] = 0.f;
#pragma unroll
            for (int p = 0; p < 9; p++) {
                float z[9];
#pragma unroll
                for (int q = 0; q < 9; q++)
                    z[q] = sY[rowmap(q, p) * HID + t];
                int cidx = 0;
#pragma unroll
                for (int n = 0; n < 9; n++)
#pragma unroll
                    for (int m = n; m < 9; m++)
                        sa[cidx++] += z[n] * z[m];
            }
            // Y fully consumed -> release it for the next batch's writeback
            if (b + 1 < bEnd) BAR_ARRIVE(4, 512);

#pragma unroll
            for (int i = 0; i < 45; i++) {
                float v = sa[i];
#pragma unroll
                for (int o = 16; o > 0; o >>= 1) v += __shfl_xor_sync(0xffffffffu, v, o);
                if (lane == 0) sRed[warpA][i] = v;
            }
            BAR_SYNC(2, 256);

            if (t < 45) {
                float s = 0.f;
#pragma unroll
                for (int w = 0; w < 8; w++) s += sRed[w][t];
                int n = 0, m = t;
                while (m >= 9 - n) { m -= (9 - n); n++; }
                m += n;
                float val = s * (1.0f / 48.0f);   // 1/sqrt(2304)
                if (n == m) val -= 100.0f;        // diagonal suppression
                sAttn[n * 9 + m] = val;
                sAttn[m * 9 + n] = val;
            }
            BAR_SYNC(2, 256);

            if (t < 81) {
                int n = t / 9, k = t % 9;
                float s = 0.f;
#pragma unroll
                for (int m = 0; m < 9; m++) s += sAttn[n * 9 + m] * sAttn[k * 9 + m];
                sB2[t] = s * (1.0f / 3.0f);
            }
            BAR_SYNC(2, 256);

            if (t < 9) {
                int n = t;
                float mx = -1e30f;
#pragma unroll
                for (int k = 0; k < 9; k++) mx = fmaxf(mx, sB2[n * 9 + k]);
                float e[9]; float se = 0.f;
#pragma unroll
                for (int k = 0; k < 9; k++) { e[k] = expf(sB2[n * 9 + k] - mx); se += e[k]; }
                float inv = 1.0f / se;
                float L[9]; float mx2 = -1e30f;
#pragma unroll
                for (int k = 0; k < 9; k++) {
                    L[k] = sAttn[n * 9 + k] + e[k] * inv;
                    mx2 = fmaxf(mx2, L[k]);
                }
                float e2[9]; float s2 = 0.f;
#pragma unroll
                for (int k = 0; k < 9; k++) { e2[k] = expf(L[k] - mx2); s2 += e2[k]; }
                float inv2 = 1.0f / s2;
#pragma unroll
                for (int k = 0; k < 9; k++) sPp[n * 12 + k] = e2[k] * inv2;
            }
            BAR_SYNC(2, 256);

            // ---- epilogue: out[n,p,c] = sum_m P[n,m] * x[rm(m,p),c] ----
            const float2* Xb2 = (const float2*)(X + (size_t)b * (HW81 * CDIM));
            float2*       Ob  = (float2*)out + (size_t)b * (HW81 * 256);

#pragma unroll
            for (int p = 0; p < 9; p++) {
                float2 v[9];
#pragma unroll
                for (int m = 0; m < 9; m++)
                    v[m] = Xb2[rowmap(m, p) * 256 + t];
#pragma unroll
                for (int n = 0; n < 9; n++) {
                    float4 w0 = *(const float4*)&sPp[n * 12 + 0];
                    float4 w1 = *(const float4*)&sPp[n * 12 + 4];
                    float  w2 = sPp[n * 12 + 8];
                    float2 o = make_float2(0.f, 0.f);
                    o.x += w0.x * v[0].x;  o.y += w0.x * v[0].y;
                    o.x += w0.y * v[1].x;  o.y += w0.y * v[1].y;
                    o.x += w0.z * v[2].x;  o.y += w0.z * v[2].y;
                    o.x += w0.w * v[3].x;  o.y += w0.w * v[3].y;
                    o.x += w1.x * v[4].x;  o.y += w1.x * v[4].y;
                    o.x += w1.y * v[5].x;  o.y += w1.y * v[5].y;
                    o.x += w1.z * v[6].x;  o.y += w1.z * v[6].y;
                    o.x += w1.w * v[7].x;  o.y += w1.w * v[7].y;
                    o.x += w2   * v[8].x;  o.y += w2   * v[8].y;
                    Ob[rowmap(n, p) * 256 + t] = o;
                }
            }
            // next loop iteration starts with BAR_SYNC(3): attn warps park
            // there while the GEMM half streams MMAs for batch b+1.
        }
    }
}

// ---------------------------------------------------------------------------
extern "C" void kernel_launch(void* const* d_in, const int* in_sizes, int n_in,
                              void* d_out, int out_size)
{
    const float* x   = (const float*)d_in[0];   // [2048, 9, 9, 512] fp32
    const float* Wf  = (const float*)d_in[1];   // [256, 512] fp32
    const float* bfc = (const float*)d_in[2];   // [256] fp32
    float* out = (float*)d_out;

    static bool init = false;
    if (!init) {
        cudaFuncSetAttribute(fused_ws,
                             cudaFuncAttributeMaxDynamicSharedMemorySize,
                             SMEM_FLOATS * 4);
        init = true;
    }

    wprep_kernel<<<256, 512>>>(Wf);
    fused_ws<<<NSM, 512, SMEM_FLOATS * 4>>>(x, bfc, out);
}

// round 16
// speedup vs baseline: 1.1452x; 1.1452x over previous
#include <cuda_runtime.h>
#include <cuda_bf16.h>
#include <stdint.h>

#define BATCH 2048
#define HW81  81
#define CDIM  512
#define HID   256

// W pre-rounded to tf32 (fp32 bit patterns), [256][512]
__device__ float g_Wt[HID * CDIM];

// ---------------------------------------------------------------------------
// helpers
// ---------------------------------------------------------------------------
__device__ __forceinline__ uint32_t f2tf32(float f) {
    uint32_t u;
    asm("cvt.rna.tf32.f32 %0, %1;" : "=r"(u) : "f"(f));
    return u;
}

__device__ __forceinline__ uint32_t smem_u32(const void* p) {
    uint32_t a;
    asm("{ .reg .u64 t; cvta.to.shared.u64 t, %1; cvt.u32.u64 %0, t; }" : "=r"(a) : "l"(p));
    return a;
}

__device__ __forceinline__ void cp16(uint32_t dst, const void* src) {
    asm volatile("cp.async.cg.shared.global [%0], [%1], 16;" :: "r"(dst), "l"(src));
}

__device__ __forceinline__ void mma_tf32(float* c, uint32_t a0, uint32_t a1,
                                         uint32_t a2, uint32_t a3,
                                         uint32_t b0, uint32_t b1) {
    asm volatile(
        "mma.sync.aligned.m16n8k8.row.col.f32.tf32.tf32.f32 "
        "{%0,%1,%2,%3}, {%4,%5,%6,%7}, {%8,%9}, {%0,%1,%2,%3};\n"
        : "+f"(c[0]), "+f"(c[1]), "+f"(c[2]), "+f"(c[3])
        : "r"(a0), "r"(a1), "r"(a2), "r"(a3), "r"(b0), "r"(b1));
}

// rm(q,p): row in x-natural order of token q of patch p's attention view
__device__ __forceinline__ int rowmap(int q, int p) {
    return (3 * (q / 3) + p / 3) * 9 + 3 * (q % 3) + (p % 3);
}

// ---------------------------------------------------------------------------
// Kernel 0: round W to tf32 (RNA) once.
// ---------------------------------------------------------------------------
__global__ void wprep_kernel(const float* __restrict__ Wf) {
    int i = blockIdx.x * 512 + threadIdx.x;
    g_Wt[i] = __uint_as_float(f2tf32(Wf[i]));
}

// ---------------------------------------------------------------------------
// Fused kernel: one CTA == one batch.  NO M padding:
//   rows 0..79 via tf32 mma.sync (5 m-tiles, warp grid 1M x 8N, tile 80x32),
//   row 80 via fp32 FMA folded into the mainloop (1 column per thread).
//   Then syrk + double softmax from smem-Y, epilogue out = P @ x.
// 256 threads = 8 warps. K staged 32 at a time, 2 cp.async stages.
// smem: 2 x (81+256) x 36 floats = 97056B dyn (Y 83KB reuses it), 2 CTAs/SM.
// ---------------------------------------------------------------------------
#define KSTG     32
#define STRIDE   36
#define A_ROWS   81
#define OFF_A0   0
#define OFF_B0   (A_ROWS * STRIDE)               /* 2916  */
#define OFF_A1   (OFF_B0 + HID * STRIDE)         /* 12132 */
#define OFF_B1   (OFF_A1 + A_ROWS * STRIDE)      /* 15048 */
#define SMEM_FLOATS (OFF_B1 + HID * STRIDE)      /* 24264 floats = 97056 B */

__global__ __launch_bounds__(256, 2)
void fused_kernel(const float* __restrict__ X, const float* __restrict__ bfc,
                  float* __restrict__ out)
{
    extern __shared__ __align__(16) float smem[];
    __shared__ float sBias[HID];
    __shared__ float sRed[8][45];
    __shared__ float sAttn[81];
    __shared__ float sB2[81];
    __shared__ __align__(16) float sPp[9 * 12];   /* P rows padded to 12 */

    const int b    = blockIdx.x;
    const int tid  = threadIdx.x;
    const int lane = tid & 31;
    const int warp = tid >> 5;
    const uint32_t sbase = smem_u32(smem);

    const float* Xb = X + (size_t)b * (HW81 * CDIM);

    sBias[tid] = __ldg(bfc + tid);

    float acc[5][4][4];
#pragma unroll
    for (int a = 0; a < 5; a++)
#pragma unroll
        for (int c = 0; c < 4; c++)
#pragma unroll
            for (int d = 0; d < 4; d++) acc[a][c][d] = 0.f;
    float s80 = 0.f;                      // row-80 dot for column `tid`

    // per stage: A 81x32 = 648 float4 (<=3/thread), B 256x32 = 2048 (8/thread)
#define ISSUE_STAGE(IT, OFFA, OFFB)                                          \
    do {                                                                     \
        const int k0 = (IT) * KSTG;                                          \
        _Pragma("unroll")                                                    \
        for (int i = 0; i < 3; i++) {                                        \
            int f = i * 256 + tid;  /* 0..767 */                             \
            if (f < 648) {                                                   \
                int r = f >> 3, j = (f & 7) << 2;                            \
                cp16(sbase + ((OFFA) + r * STRIDE + j) * 4,                  \
                     Xb + (size_t)r * CDIM + k0 + j);                        \
            }                                                                \
        }                                                                    \
        _Pragma("unroll")                                                    \
        for (int i = 0; i < 8; i++) {                                        \
            int f = i * 256 + tid;  /* 0..2047 */                            \
            int n = f >> 3, j = (f & 7) << 2;                                \
            cp16(sbase + ((OFFB) + n * STRIDE + j) * 4,                     \
                 g_Wt + (size_t)n * CDIM + k0 + j);                         \
        }                                                                    \
        asm volatile("cp.async.commit_group;" ::: "memory");                 \
    } while (0)

    ISSUE_STAGE(0, OFF_A0, OFF_B0);
    ISSUE_STAGE(1, OFF_A1, OFF_B1);

    const int ar = lane >> 2;            // 0..7
    const int ac = lane & 3;
    const int bn = warp * 32 + (lane >> 2);

    for (int it = 0; it < 16; it++) {
        if (it < 15) asm volatile("cp.async.wait_group 1;" ::: "memory");
        else         asm volatile("cp.async.wait_group 0;" ::: "memory");
        __syncthreads();

        const float*    sA  = smem + ((it & 1) ? OFF_A1 : OFF_A0);
        const uint32_t* sB  = (const uint32_t*)(smem + ((it & 1) ? OFF_B1 : OFF_B0));
        const float*    sBf = (const float*)sB;

#pragma unroll
        for (int kk = 0; kk < 4; kk++) {
            const int c = kk * 8 + ac;
            uint32_t bf[4][2];
#pragma unroll
            for (int nt = 0; nt < 4; nt++) {
                bf[nt][0] = sB[(bn + nt * 8) * STRIDE + c];
                bf[nt][1] = sB[(bn + nt * 8) * STRIDE + c + 4];
            }
#pragma unroll
            for (int mt = 0; mt < 5; mt++) {
                const int r = ar + mt * 16;
                uint32_t a0 = f2tf32(sA[r * STRIDE + c]);
                uint32_t a1 = f2tf32(sA[(r + 8) * STRIDE + c]);
                uint32_t a2 = f2tf32(sA[r * STRIDE + c + 4]);
                uint32_t a3 = f2tf32(sA[(r + 8) * STRIDE + c + 4]);
#pragma unroll
                for (int nt = 0; nt < 4; nt++)
                    mma_tf32(acc[mt][nt], a0, a1, a2, a3, bf[nt][0], bf[nt][1]);
            }
        }

        // ---- row 80 via FMA: thread owns column `tid` ----
#pragma unroll
        for (int k4 = 0; k4 < 8; k4++) {
            float4 av = *(const float4*)&sA[80 * STRIDE + k4 * 4];     // broadcast
            float4 wv = *(const float4*)&sBf[tid * STRIDE + k4 * 4];   // conflict-free
            s80 += av.x * wv.x + av.y * wv.y + av.z * wv.z + av.w * wv.w;
        }

        __syncthreads();

        if (it < 14) {
            if (it & 1) ISSUE_STAGE(it + 2, OFF_A1, OFF_B1);
            else        ISSUE_STAGE(it + 2, OFF_A0, OFF_B0);
        }
    }

    // ---- write Y + bias into smem, reusing staging ----
    __syncthreads();           // all warps done reading stage buffers
    float* sY = smem;          // [81][256] = 20736 floats <= 24264
#pragma unroll
    for (int nt = 0; nt < 4; nt++) {
        const int cc = warp * 32 + nt * 8 + ((lane & 3) << 1);
        const float b0 = sBias[cc];
        const float b1 = sBias[cc + 1];
#pragma unroll
        for (int mt = 0; mt < 5; mt++) {
            const int r = ar + mt * 16;
            sY[r * HID + cc]           = acc[mt][nt][0] + b0;
            sY[r * HID + cc + 1]       = acc[mt][nt][1] + b1;
            sY[(r + 8) * HID + cc]     = acc[mt][nt][2] + b0;
            sY[(r + 8) * HID + cc + 1] = acc[mt][nt][3] + b1;
        }
    }
    sY[80 * HID + tid] = s80 + sBias[tid];
    __syncthreads();

    // ---- syrk: attn[n,m] = (1/48) sum_{p,h} Y[rm(n,p),h] Y[rm(m,p),h] ----
    {
        float sa[45];
#pragma unroll
        for (int i = 0; i < 45; i++) sa[i] = 0.f;

        float zz[2][9];
#pragma unroll
        for (int q = 0; q < 9; q++)
            zz[0][q] = sY[rowmap(q, 0) * HID + tid];

#pragma unroll
        for (int p = 0; p < 9; p++) {
            const int cur = p & 1;
            if (p < 8) {
#pragma unroll
                for (int q = 0; q < 9; q++)
                    zz[cur ^ 1][q] = sY[rowmap(q, p + 1) * HID + tid];
            }
            int cidx = 0;
#pragma unroll
            for (int n = 0; n < 9; n++)
#pragma unroll
                for (int m = n; m < 9; m++)
                    sa[cidx++] += zz[cur][n] * zz[cur][m];
        }
#pragma unroll
        for (int i = 0; i < 45; i++) {
            float v = sa[i];
#pragma unroll
            for (int o = 16; o > 0; o >>= 1) v += __shfl_xor_sync(0xffffffffu, v, o);
            if (lane == 0) sRed[warp][i] = v;
        }
    }
    __syncthreads();

    // ---- early prefetch of epilogue v for p=0 (independent of P) ----
    const float2* Xb2 = (const float2*)Xb;                       // [81][256]
    float2 v[2][9];
#pragma unroll
    for (int m = 0; m < 9; m++)
        v[0][m] = Xb2[rowmap(m, 0) * 256 + tid];

    if (tid < 45) {
        float s = 0.f;
#pragma unroll
        for (int w = 0; w < 8; w++) s += sRed[w][tid];
        int n = 0, m = tid;
        while (m >= 9 - n) { m -= (9 - n); n++; }
        m += n;
        float val = s * (1.0f / 48.0f);   // (hidden*P)^-0.5 = 1/sqrt(2304)
        if (n == m) val -= 100.0f;        // diagonal self-suppression
        sAttn[n * 9 + m] = val;
        sAttn[m * 9 + n] = val;
    }
    __syncthreads();

    if (tid < 81) {
        int n = tid / 9, k = tid % 9;
        float s = 0.f;
#pragma unroll
        for (int m = 0; m < 9; m++) s += sAttn[n * 9 + m] * sAttn[k * 9 + m];
        sB2[tid] = s * (1.0f / 3.0f);
    }
    __syncthreads();

    if (tid < 9) {
        int n = tid;
        float mx = -1e30f;
#pragma unroll
        for (int k = 0; k < 9; k++) mx = fmaxf(mx, sB2[n * 9 + k]);
        float e[9]; float se = 0.f;
#pragma unroll
        for (int k = 0; k < 9; k++) { e[k] = expf(sB2[n * 9 + k] - mx); se += e[k]; }
        float inv = 1.0f / se;
        float L[9]; float mx2 = -1e30f;
#pragma unroll
        for (int k = 0; k < 9; k++) {
            L[k] = sAttn[n * 9 + k] + e[k] * inv;
            mx2 = fmaxf(mx2, L[k]);
        }
        float e2[9]; float s2 = 0.f;
#pragma unroll
        for (int k = 0; k < 9; k++) { e2[k] = expf(L[k] - mx2); s2 += e2[k]; }
        float inv2 = 1.0f / s2;
#pragma unroll
        for (int k = 0; k < 9; k++) sPp[n * 12 + k] = e2[k] * inv2;
    }
    __syncthreads();

    // ---- epilogue: out[n,p,c] = sum_m P[n,m] * x[rm(m,p),c] ----
    float2* Ob = (float2*)out + (size_t)b * (HW81 * 256);

#pragma unroll
    for (int p = 0; p < 9; p++) {
        const int cur = p & 1;
        if (p < 8) {
#pragma unroll
            for (int m = 0; m < 9; m++)
                v[cur ^ 1][m] = Xb2[rowmap(m, p + 1) * 256 + tid];
        }
#pragma unroll
        for (int n = 0; n < 9; n++) {
            float4 w0 = *(const float4*)&sPp[n * 12 + 0];
            float4 w1 = *(const float4*)&sPp[n * 12 + 4];
            float  w2 = sPp[n * 12 + 8];
            float2 o = make_float2(0.f, 0.f);
            o.x += w0.x * v[cur][0].x;  o.y += w0.x * v[cur][0].y;
            o.x += w0.y * v[cur][1].x;  o.y += w0.y * v[cur][1].y;
            o.x += w0.z * v[cur][2].x;  o.y += w0.z * v[cur][2].y;
            o.x += w0.w * v[cur][3].x;  o.y += w0.w * v[cur][3].y;
            o.x += w1.x * v[cur][4].x;  o.y += w1.x * v[cur][4].y;
            o.x += w1.y * v[cur][5].x;  o.y += w1.y * v[cur][5].y;
            o.x += w1.z * v[cur][6].x;  o.y += w1.z * v[cur][6].y;
            o.x += w1.w * v[cur][7].x;  o.y += w1.w * v[cur][7].y;
            o.x += w2   * v[cur][8].x;  o.y += w2   * v[cur][8].y;
            Ob[rowmap(n, p) * 256 + tid] = o;
        }
    }
}

// ---------------------------------------------------------------------------
extern "C" void kernel_launch(void* const* d_in, const int* in_sizes, int n_in,
                              void* d_out, int out_size)
{
    const float* x   = (const float*)d_in[0];   // [2048, 9, 9, 512] fp32
    const float* Wf  = (const float*)d_in[1];   // [256, 512] fp32
    const float* bfc = (const float*)d_in[2];   // [256] fp32
    float* out = (float*)d_out;

    static bool init = false;
    if (!init) {
        cudaFuncSetAttribute(fused_kernel,
                             cudaFuncAttributeMaxDynamicSharedMemorySize,
                             SMEM_FLOATS * 4);
        init = true;
    }

    wprep_kernel<<<256, 512>>>(Wf);
    fused_kernel<<<BATCH, 256, SMEM_FLOATS * 4>>>(x, bfc, out);
}